// round 2
// baseline (speedup 1.0000x reference)
#include <cuda_runtime.h>
#include <cstdint>

#define CAPL   65536
#define NMSCAP 5000
#define NEGV   (-1000000000.0f)
#define BBOXCL 4.135166556742356f

// ------------------------- device scratch (no allocs) -----------------------
__device__ float g_bufA[7782400];
__device__ float g_bufB[7782400];
__device__ float g_cls[33197346];
__device__ float g_reg[1459224];
__device__ float g_mu[64];
__device__ float g_var[64];
__device__ unsigned long long g_k64[10 * CAPL];
__device__ int   g_cnt[10];
__device__ float g_nbox[2 * NMSCAP * 4];

__constant__ int  c_HW[5]     = {15200, 3800, 950, 247, 70};
__constant__ long c_regoff[5] = {0, 1094400, 1368000, 1436400, 1454184};
__constant__ int  c_ancoff[5] = {0, 136800, 171000, 179550, 181773};

__device__ __forceinline__ float* selbuf(int s, long off) {
    if (s == 0) return g_bufA + off;
    if (s == 1) return g_bufB + off;
    if (s == 2) return g_cls  + off;
    return g_reg + off;
}

// ------------------------- conv 3x3 SAME, Cin=256, fp32 ---------------------
// block 256 thr = 64 oc x (8x8 px); per-thread 4 oc x 4 px
__global__ __launch_bounds__(256) void conv3x3(
    const float* __restrict__ xext, int xsel, int ysel, long yoff,
    const float* __restrict__ wgt, const float* __restrict__ bias,
    int OC, int H, int W)
{
    __shared__ float xs[16 * 110];                    // 16 ic x 10x10 (stride 11)
    __shared__ __align__(16) float ws[144 * 68];      // [ic*9+tap][oc0..63]

    const float* x = xext ? xext : selbuf(xsel, 0);
    float* y = selbuf(ysel, yoff);

    const int t = threadIdx.x;
    const int octiles = gridDim.z >> 1;
    const int n   = blockIdx.z / octiles;
    const int oc0 = (blockIdx.z % octiles) * 64;
    const int h0 = blockIdx.y * 8, w0 = blockIdx.x * 8;
    const int oc_id = t >> 4;            // 0..15
    const int px_id = t & 15;
    const int ph  = px_id >> 1;          // 0..7
    const int pw0 = (px_id & 1) * 4;     // 0 or 4

    float acc[4][4] = {};

    for (int ic0 = 0; ic0 < 256; ic0 += 16) {
        for (int d = t; d < 1600; d += 256) {
            int ic = d / 100, r = d - ic * 100;
            int iy = r / 10, ix = r - iy * 10;
            int gy = h0 - 1 + iy, gx = w0 - 1 + ix;
            float v = 0.f;
            if ((unsigned)gy < (unsigned)H && (unsigned)gx < (unsigned)W)
                v = x[(((long)(n * 256 + ic0 + ic)) * H + gy) * W + gx];
            xs[ic * 110 + iy * 11 + ix] = v;
        }
        for (int d = t; d < 9216; d += 256) {
            int oc = d / 144, r = d - oc * 144;
            int oca = oc0 + oc;
            float v = 0.f;
            if (oca < OC) v = wgt[((long)oca * 256 + ic0) * 9 + r];
            ws[r * 68 + oc] = v;
        }
        __syncthreads();

#pragma unroll 4
        for (int ic = 0; ic < 16; ic++) {
#pragma unroll
            for (int ky = 0; ky < 3; ky++) {
                float xv[6];
#pragma unroll
                for (int j = 0; j < 6; j++)
                    xv[j] = xs[ic * 110 + (ph + ky) * 11 + pw0 + j];
#pragma unroll
                for (int kx = 0; kx < 3; kx++) {
                    const float4 wv = *reinterpret_cast<const float4*>(
                        &ws[(ic * 9 + ky * 3 + kx) * 68 + (oc_id << 2)]);
#pragma unroll
                    for (int j = 0; j < 4; j++) {
                        acc[0][j] += wv.x * xv[kx + j];
                        acc[1][j] += wv.y * xv[kx + j];
                        acc[2][j] += wv.z * xv[kx + j];
                        acc[3][j] += wv.w * xv[kx + j];
                    }
                }
            }
        }
        __syncthreads();
    }

    const int h = h0 + ph;
    if (h < H) {
#pragma unroll
        for (int i = 0; i < 4; i++) {
            int oc = oc0 + (oc_id << 2) + i;
            if (oc < OC) {
                float bv = bias[oc];
#pragma unroll
                for (int j = 0; j < 4; j++) {
                    int w = w0 + pw0 + j;
                    if (w < W)
                        y[(((long)(n * OC + oc)) * H + h) * W + w] = acc[i][j] + bv;
                }
            }
        }
    }
}

// ------------------------- GroupNorm ---------------------------------------
__global__ __launch_bounds__(256) void gn_stats(int xsel, int HW)
{
    const int b = blockIdx.x;                 // n*32+g
    const int n = b >> 5, g = b & 31;
    const float* p = selbuf(xsel, 0) + (long)(n * 256 + g * 8) * HW;
    const int total = 8 * HW;
    double s = 0.0, ss = 0.0;
    for (int i = threadIdx.x; i < total; i += 256) {
        float v = p[i];
        s += v; ss += (double)v * (double)v;
    }
    __shared__ double rs[256], rq[256];
    rs[threadIdx.x] = s; rq[threadIdx.x] = ss;
    __syncthreads();
    for (int o = 128; o; o >>= 1) {
        if (threadIdx.x < o) { rs[threadIdx.x] += rs[threadIdx.x+o]; rq[threadIdx.x] += rq[threadIdx.x+o]; }
        __syncthreads();
    }
    if (threadIdx.x == 0) {
        double mu = rs[0] / total;
        g_mu[b]  = (float)mu;
        g_var[b] = (float)(rq[0] / total - mu * mu);
    }
}

__global__ void gn_norm(int xsel, int ysel,
                        const float* __restrict__ gs, const float* __restrict__ gb, int HW)
{
    int idx = blockIdx.x * blockDim.x + threadIdx.x;
    int per_n = 256 * HW;
    if (idx >= 2 * per_n) return;
    int n = idx / per_n;
    int r = idx - n * per_n;
    int c = r / HW;
    int b = n * 32 + (c >> 3);
    float inv = rsqrtf(g_var[b] + 1e-5f);
    float v = (selbuf(xsel,0)[idx] - g_mu[b]) * inv * gs[c] + gb[c];
    selbuf(ysel,0)[idx] = fmaxf(v, 0.f);
}

// ------------------------- candidates / sort / nms --------------------------
__global__ void zero_cnt() { if (threadIdx.x < 10) g_cnt[threadIdx.x] = 0; }

__global__ void cand_k(long clsoff, int per_n, int HW, int level)
{
    int idx = blockIdx.x * blockDim.x + threadIdx.x;
    if (idx >= 2 * per_n) return;
    int n = idx / per_n;
    int r = idx - n * per_n;
    float sg = 1.0f / (1.0f + expf(-g_cls[clsoff + idx]));
    if (sg > 0.05f) {
        int ch = r / HW;
        int s  = r - ch * HW;
        int a  = ch / 91, c = ch - a * 91;
        unsigned flat = (unsigned)(((s * 9 + a) * 91) + c);
        unsigned key = ((unsigned)level << 24) | flat;
        int pos = atomicAdd(&g_cnt[n * 5 + level], 1);
        if (pos < CAPL) {
            unsigned sb = __float_as_uint(sg);
            g_k64[(long)(n * 5 + level) * CAPL + pos] =
                (((unsigned long long)(0xFFFFFFFFu - sb)) << 32) | key;
        }
    }
}

// global-memory bitonic sort, one 1024-thread block per (n,level) list
__global__ __launch_bounds__(1024) void sort_k()
{
    const int b = blockIdx.x;
    unsigned long long* v = g_k64 + (long)b * CAPL;
    int cnt = g_cnt[b]; if (cnt > CAPL) cnt = CAPL;
    if (cnt <= 1) return;
    int n2 = 1; while (n2 < cnt) n2 <<= 1;
    for (int i = cnt + threadIdx.x; i < n2; i += 1024) v[i] = ~0ull;
    __syncthreads();
    for (int k = 2; k <= n2; k <<= 1) {
        for (int j = k >> 1; j > 0; j >>= 1) {
            for (int i = threadIdx.x; i < n2; i += 1024) {
                int ixj = i ^ j;
                if (ixj > i) {
                    unsigned long long a = v[i], c2 = v[ixj];
                    if ((a > c2) == ((i & k) == 0)) { v[i] = c2; v[ixj] = a; }
                }
            }
            __syncthreads();
        }
    }
}

extern __shared__ unsigned char s_raw[];

__global__ __launch_bounds__(256) void nms_k(const float* __restrict__ anc,
                                             float* __restrict__ out)
{
    const int n = blockIdx.x;
    float*    sws  = (float*)s_raw;                   // [5000]
    float*    sbo  = (float*)s_raw + 5008;            // [20000]
    unsigned* skey = (unsigned*)((float*)s_raw + 25008); // [5000]
    __shared__ float rbs[256];
    __shared__ unsigned rbk[256];
    __shared__ int rbi[256];

    int Ls[5], offs[5], K = 0;
    for (int l = 0; l < 5; l++) {
        int c = g_cnt[n * 5 + l];
        if (c > CAPL) c = CAPL;
        if (c > 1000) c = 1000;
        offs[l] = K; Ls[l] = c; K += c;
    }

    for (int idx = threadIdx.x; idx < K; idx += 256) {
        int l = 0;
        while (l < 4 && idx >= offs[l] + Ls[l]) l++;
        int kin = idx - offs[l];
        unsigned long long v = g_k64[(long)(n * 5 + l) * CAPL + kin];
        unsigned key = (unsigned)v;
        float sc = __uint_as_float(0xFFFFFFFFu - (unsigned)(v >> 32));
        int flat = (int)(key & 0xFFFFFFu);
        int ai = flat / 91, c = flat - ai * 91;
        int sidx = ai / 9, a = ai - sidx * 9;
        int HW = c_HW[l];
        const float* rp = g_reg + c_regoff[l] + (long)(n * 36 + a * 4) * HW + sidx;
        float dx = rp[0], dy = rp[HW], dw = rp[2*HW], dh = rp[3*HW];
        int gidx = c_ancoff[l] + ai;
        float ax0 = anc[4*gidx], ay0 = anc[4*gidx+1], ax1 = anc[4*gidx+2], ay1 = anc[4*gidx+3];
        float aw = ax1 - ax0, ah = ay1 - ay0;
        float cx = ax0 + 0.5f * aw, cy = ay0 + 0.5f * ah;
        dw = fminf(dw, BBOXCL); dh = fminf(dh, BBOXCL);
        float pcx = dx * aw + cx, pcy = dy * ah + cy;
        float pw = expf(dw) * aw, phh = expf(dh) * ah;
        float b0 = fminf(fmaxf(pcx - 0.5f*pw , 0.f), 1216.f);
        float b1 = fminf(fmaxf(pcy - 0.5f*phh, 0.f),  800.f);
        float b2 = fminf(fmaxf(pcx + 0.5f*pw , 0.f), 1216.f);
        float b3 = fminf(fmaxf(pcy + 0.5f*phh, 0.f),  800.f);
        float* nb = &g_nbox[(n * NMSCAP + idx) * 4];
        nb[0]=b0; nb[1]=b1; nb[2]=b2; nb[3]=b3;
        float off = (float)c * 2017.0f;
        sbo[idx*4+0]=b0+off; sbo[idx*4+1]=b1+off; sbo[idx*4+2]=b2+off; sbo[idx*4+3]=b3+off;
        sws[idx] = sc; skey[idx] = key;
    }
    __syncthreads();

    int m = 0;
    for (; m < 300; m++) {
        float bs = -1e30f; unsigned bk = 0xFFFFFFFFu; int bi = -1;
        for (int k = threadIdx.x; k < K; k += 256) {
            float s = sws[k];
            if (s > bs || (s == bs && skey[k] < bk)) { bs = s; bk = skey[k]; bi = k; }
        }
        rbs[threadIdx.x]=bs; rbk[threadIdx.x]=bk; rbi[threadIdx.x]=bi;
        __syncthreads();
        for (int o = 128; o; o >>= 1) {
            if (threadIdx.x < o) {
                float s2 = rbs[threadIdx.x+o];
                if (s2 > rbs[threadIdx.x] ||
                    (s2 == rbs[threadIdx.x] && rbk[threadIdx.x+o] < rbk[threadIdx.x])) {
                    rbs[threadIdx.x]=s2; rbk[threadIdx.x]=rbk[threadIdx.x+o]; rbi[threadIdx.x]=rbi[threadIdx.x+o];
                }
            }
            __syncthreads();
        }
        bs = rbs[0]; bi = rbi[0]; bk = rbk[0];
        if (bs <= 0.0f) break;
        if (threadIdx.x == 0) {
            float* nb = &g_nbox[(n * NMSCAP + bi) * 4];
            out[n*1200 + m*4+0]=nb[0]; out[n*1200 + m*4+1]=nb[1];
            out[n*1200 + m*4+2]=nb[2]; out[n*1200 + m*4+3]=nb[3];
            out[2400 + n*300 + m] = bs;
            out[3000 + n*300 + m] = (float)((bk & 0xFFFFFFu) % 91u);
        }
        float jb0=sbo[bi*4+0], jb1=sbo[bi*4+1], jb2=sbo[bi*4+2], jb3=sbo[bi*4+3];
        float ja = (jb2-jb0)*(jb3-jb1);
        for (int k = threadIdx.x; k < K; k += 256) {
            float x0 = fmaxf(jb0, sbo[k*4+0]);
            float y0 = fmaxf(jb1, sbo[k*4+1]);
            float x1 = fminf(jb2, sbo[k*4+2]);
            float y1 = fminf(jb3, sbo[k*4+3]);
            float iw = fmaxf(x1-x0, 0.f), ih = fmaxf(y1-y0, 0.f);
            float inter = iw*ih;
            float a2 = (sbo[k*4+2]-sbo[k*4+0])*(sbo[k*4+3]-sbo[k*4+1]);
            if (inter / (ja + a2 - inter + 1e-9f) > 0.5f) sws[k] = NEGV;
        }
        __syncthreads();
    }
    for (int slot = m + (int)threadIdx.x; slot < 300; slot += 256) {
        out[n*1200 + slot*4+0]=0.f; out[n*1200 + slot*4+1]=0.f;
        out[n*1200 + slot*4+2]=0.f; out[n*1200 + slot*4+3]=0.f;
        out[2400 + n*300 + slot] = 0.f;
        out[3000 + n*300 + slot] = -1.f;
    }
}

// ------------------------- host --------------------------------------------
extern "C" void kernel_launch(void* const* d_in, const int* in_sizes, int n_in,
                              void* d_out, int out_size)
{
    const float* feats[5];
    for (int i = 0; i < 5; i++) feats[i] = (const float*)d_in[i];
    const float* cls_tw = (const float*)d_in[5];
    const float* cls_tb = (const float*)d_in[6];
    const float* cls_gs = (const float*)d_in[7];
    const float* cls_gb = (const float*)d_in[8];
    const float* cls_w  = (const float*)d_in[9];
    const float* cls_b  = (const float*)d_in[10];
    const float* reg_tw = (const float*)d_in[11];
    const float* reg_tb = (const float*)d_in[12];
    const float* reg_gs = (const float*)d_in[13];
    const float* reg_gb = (const float*)d_in[14];
    const float* reg_w  = (const float*)d_in[15];
    const float* reg_b  = (const float*)d_in[16];
    const float* anchors = (const float*)d_in[17];
    float* out = (float*)d_out;

    static const int  Hs[5] = {100, 50, 25, 13, 7};
    static const int  Ws[5] = {152, 76, 38, 19, 10};
    static const long clsoff[5] = {0, 24897600, 31122000, 32678100, 33082686};
    static const long regoff[5] = {0, 1094400, 1368000, 1436400, 1454184};

    cudaFuncSetAttribute(nms_k, cudaFuncAttributeMaxDynamicSharedMemorySize, 122880);

    for (int l = 0; l < 5; l++) {
        int H = Hs[l], W = Ws[l], HW = H * W;
        dim3 g4((W + 7) / 8, (H + 7) / 8, 2 * 4);
        int nthr = (2 * 256 * HW + 255) / 256;

        // cls tower + head
        for (int i = 0; i < 4; i++) {
            conv3x3<<<g4, 256>>>(i == 0 ? feats[l] : nullptr, 1, 0, 0,
                                 cls_tw + (long)i * 256 * 256 * 9, cls_tb + i * 256, 256, H, W);
            gn_stats<<<64, 256>>>(0, HW);
            gn_norm<<<nthr, 256>>>(0, 1, cls_gs + i * 256, cls_gb + i * 256, HW);
        }
        dim3 gc((W + 7) / 8, (H + 7) / 8, 2 * 13);
        conv3x3<<<gc, 256>>>(nullptr, 1, 2, clsoff[l], cls_w, cls_b, 819, H, W);

        // reg tower + head
        for (int i = 0; i < 4; i++) {
            conv3x3<<<g4, 256>>>(i == 0 ? feats[l] : nullptr, 1, 0, 0,
                                 reg_tw + (long)i * 256 * 256 * 9, reg_tb + i * 256, 256, H, W);
            gn_stats<<<64, 256>>>(0, HW);
            gn_norm<<<nthr, 256>>>(0, 1, reg_gs + i * 256, reg_gb + i * 256, HW);
        }
        dim3 gr((W + 7) / 8, (H + 7) / 8, 2 * 1);
        conv3x3<<<gr, 256>>>(nullptr, 1, 3, regoff[l], reg_w, reg_b, 36, H, W);
    }

    zero_cnt<<<1, 32>>>();
    for (int l = 0; l < 5; l++) {
        int HW = Hs[l] * Ws[l];
        int per_n = 819 * HW;
        cand_k<<<(2 * per_n + 255) / 256, 256>>>(clsoff[l], per_n, HW, l);
    }
    sort_k<<<10, 1024>>>();
    nms_k<<<2, 256, 122880>>>(anchors, out);
}